// round 8
// baseline (speedup 1.0000x reference)
#include <cuda_runtime.h>
#include <math_constants.h>

// RoIPool: input (N=2, C=256, H=50, W=50) f32, rois (K=256, 5) f32
// output (K, C, 7, 7) f32. scale = 0.0625, P = 7.
//
// R7: smem patch staging. Block = (ROI, 64-channel quarter). For each of
// 4 chunks of 16 channels: cooperatively load the ROI's <=20x20 patch
// per channel from gmem with COALESCED row loads (lanes along w), then
// compute 7x7 outputs per channel from smem with the unrolled predicated
// 4x4 window. This replaces R6's scattered L1 gather wavefronts (L1=60%)
// with ~1-2-wavefront coalesced loads + cheap LDS.
// Block-uniform fallback to direct gather if the patch doesn't fit or a
// window span exceeds 4 (not reachable with this data distribution).

#define P 7
#define PP (P * P)
#define C_DIM 256
#define H_DIM 50
#define W_DIM 50
#define HW (H_DIM * W_DIM)
#define SCALE 0.0625f
#define ELEMS (C_DIM * PP)     // 12544 outputs per ROI
#define SPLIT 4                // blocks per ROI (channel quarters)
#define NC 16                  // channels staged per chunk
#define NCHUNK (C_DIM / SPLIT / NC)  // 4 chunks per block
#define PATCH_H 20
#define PATCH_W 21             // padded row stride (floats)
#define SPAN 4

__global__ __launch_bounds__(256) void roipool_kernel(const float* __restrict__ x,
                                                      const float* __restrict__ rois,
                                                      float* __restrict__ out)
{
    const int k    = blockIdx.x / SPLIT;
    const int part = blockIdx.x - k * SPLIT;
    const int tid  = threadIdx.x;
    const int wp   = tid >> 5;
    const int lane = tid & 31;

    __shared__ int s_hs[P], s_he[P], s_ws[P], s_we[P];
    __shared__ int s_b;
    __shared__ float patch[NC][PATCH_H][PATCH_W];   // 26.9 KB

    if (tid < P) {
        const float* r = rois + k * 5;
        float x1 = rintf(r[1] * SCALE);
        float y1 = rintf(r[2] * SCALE);
        float x2 = rintf(r[3] * SCALE);
        float y2 = rintf(r[4] * SCALE);

        float bin_w = fmaxf(x2 - x1 + 1.0f, 1.0f) * (1.0f / P);
        float bin_h = fmaxf(y2 - y1 + 1.0f, 1.0f) * (1.0f / P);

        float p = (float)tid;
        s_hs[tid] = (int)fminf(fmaxf(floorf(p * bin_h) + y1, 0.0f), (float)H_DIM);
        s_he[tid] = (int)fminf(fmaxf(ceilf((p + 1.0f) * bin_h) + y1, 0.0f), (float)H_DIM);
        s_ws[tid] = (int)fminf(fmaxf(floorf(p * bin_w) + x1, 0.0f), (float)W_DIM);
        s_we[tid] = (int)fminf(fmaxf(ceilf((p + 1.0f) * bin_w) + x1, 0.0f), (float)W_DIM);
        if (tid == 0) s_b = (int)r[0];
    }
    __syncthreads();

    const int h0 = s_hs[0];
    const int w0 = s_ws[0];
    const int pH = s_he[P - 1] - h0;
    const int pW = s_we[P - 1] - w0;

    // Block-uniform fits check (patch size + max window span).
    bool fits = (pH <= PATCH_H) && (pW <= PATCH_W - 1);
    #pragma unroll
    for (int i = 0; i < P; ++i) {
        fits = fits && (s_he[i] - s_hs[i] <= SPAN) && (s_we[i] - s_ws[i] <= SPAN);
    }

    const int cpart = part * (C_DIM / SPLIT);   // first channel of this block
    const size_t img = (size_t)s_b * C_DIM * HW;

    if (fits) {
        for (int chunk = 0; chunk < NCHUNK; ++chunk) {
            const int cbase = cpart + chunk * NC;
            const float* gb = x + img + (size_t)cbase * HW + h0 * W_DIM + w0;

            // Load phase: warp wp loads rows h = wp, wp+8, ... lanes along w.
            #pragma unroll
            for (int ch = 0; ch < NC; ++ch) {
                const float* g = gb + ch * HW;
                for (int h = wp; h < pH; h += 8) {
                    if (lane < pW) patch[ch][h][lane] = g[h * W_DIM + lane];
                }
            }
            __syncthreads();

            // Compute phase: NC*49 = 784 outputs, thread-strided.
            for (int o = tid; o < NC * PP; o += 256) {
                const int ch  = o / PP;
                const int pos = o - ch * PP;
                const int ph  = pos / P;
                const int pw  = pos - ph * P;

                const int hs = s_hs[ph] - h0, he = s_he[ph] - h0;
                const int ws = s_ws[pw] - w0, we = s_we[pw] - w0;

                float m = -CUDART_INF_F;
                #pragma unroll
                for (int dh = 0; dh < SPAN; ++dh) {
                    const bool hok = (hs + dh < he);
                    #pragma unroll
                    for (int dw = 0; dw < SPAN; ++dw) {
                        if (hok && (ws + dw < we)) {
                            m = fmaxf(m, patch[ch][hs + dh][ws + dw]);
                        }
                    }
                }
                const bool valid = (he > hs) && (we > ws);
                out[(size_t)k * ELEMS + (size_t)(cbase + ch) * PP + pos] = valid ? m : 0.0f;
            }
            __syncthreads();
        }
    } else {
        // Fallback: direct gather with dynamic bounds (not hit by this data).
        for (int o = tid; o < (C_DIM / SPLIT) * PP; o += 256) {
            const int ch  = o / PP;
            const int pos = o - ch * PP;
            const int ph  = pos / P;
            const int pw  = pos - ph * P;

            const int hs = s_hs[ph], he = s_he[ph];
            const int ws = s_ws[pw], we = s_we[pw];

            float m = 0.0f;
            if (he > hs && we > ws) {
                m = -CUDART_INF_F;
                const float* p0 = x + img + (size_t)(cpart + ch) * HW;
                for (int h = hs; h < he; ++h) {
                    const float* row = p0 + h * W_DIM;
                    for (int w = ws; w < we; ++w) m = fmaxf(m, row[w]);
                }
            }
            out[(size_t)k * ELEMS + (size_t)(cpart + ch) * PP + pos] = m;
        }
    }
}

extern "C" void kernel_launch(void* const* d_in, const int* in_sizes, int n_in,
                              void* d_out, int out_size)
{
    const float* x    = (const float*)d_in[0];
    const float* rois = (const float*)d_in[1];
    float* out        = (float*)d_out;

    int K = out_size / ELEMS;   // 256
    roipool_kernel<<<K * SPLIT, 256>>>(x, rois, out);
}

// round 9
// speedup vs baseline: 2.1048x; 2.1048x over previous
#include <cuda_runtime.h>
#include <math_constants.h>

// RoIPool: input (N=2, C=256, H=50, W=50) f32, rois (K=256, 5) f32
// output (K, C, 7, 7) f32. scale = 0.0625, P = 7.
//
// R8: warp-cooperative rows. Warp = (ROI, 16-channel group, ph).
// hs/he depend only on ph -> warp-uniform row loop, zero h-divergence.
// Lanes are w-columns of the <=18-wide ROI patch -> every LDG is a
// coalesced ~3-sector row read (vs R6's scattered gathers, L1=60%).
// Per lane: running row-max per channel in registers; stash to a
// per-warp smem strip; __syncwarp; lanes then produce the 112 outputs
// with <=4 predicated LDS each.
// Block-uniform fallback (pW>32) keeps correctness for any ROI size.

#define P 7
#define PP 49
#define C_DIM 256
#define H_DIM 50
#define W_DIM 50
#define HW 2500
#define SCALE 0.0625f
#define ELEMS (C_DIM * PP)              // 12544 per ROI
#define CPW 16                          // channels per warp
#define WARPS_PER_ROI ((C_DIM / CPW) * P)   // 112
#define BLOCKS_PER_ROI (WARPS_PER_ROI / 8)  // 14
#define MS_STRIDE 36                    // padded row stride (floats)

__global__ __launch_bounds__(256) void roipool_kernel(const float* __restrict__ x,
                                                      const float* __restrict__ rois,
                                                      float* __restrict__ out)
{
    const int k    = blockIdx.x / BLOCKS_PER_ROI;
    const int part = blockIdx.x - k * BLOCKS_PER_ROI;
    const int tid  = threadIdx.x;
    const int wid  = tid >> 5;
    const int lane = tid & 31;

    __shared__ int s_hs[P], s_he[P], s_ws[P], s_we[P];
    __shared__ int s_b;
    __shared__ float s_m[8][CPW][MS_STRIDE];   // 18.4 KB

    if (tid < P) {
        const float* r = rois + k * 5;
        float x1 = rintf(r[1] * SCALE);
        float y1 = rintf(r[2] * SCALE);
        float x2 = rintf(r[3] * SCALE);
        float y2 = rintf(r[4] * SCALE);

        float bin_w = fmaxf(x2 - x1 + 1.0f, 1.0f) * (1.0f / P);
        float bin_h = fmaxf(y2 - y1 + 1.0f, 1.0f) * (1.0f / P);

        float p = (float)tid;
        s_hs[tid] = (int)fminf(fmaxf(floorf(p * bin_h) + y1, 0.0f), (float)H_DIM);
        s_he[tid] = (int)fminf(fmaxf(ceilf((p + 1.0f) * bin_h) + y1, 0.0f), (float)H_DIM);
        s_ws[tid] = (int)fminf(fmaxf(floorf(p * bin_w) + x1, 0.0f), (float)W_DIM);
        s_we[tid] = (int)fminf(fmaxf(ceilf((p + 1.0f) * bin_w) + x1, 0.0f), (float)W_DIM);
        if (tid == 0) s_b = (int)r[0];
    }
    __syncthreads();

    const int w0 = s_ws[0];
    const int pW = s_we[P - 1] - w0;

    int maxspan = 0;
    #pragma unroll
    for (int i = 0; i < P; ++i) maxspan = max(maxspan, s_we[i] - s_ws[i]);

    const int task = part * 8 + wid;        // 0..111
    const int cg   = task / P;              // 0..15
    const int ph   = task - cg * P;
    const int c0   = cg * CPW;
    const int hs   = s_hs[ph], he = s_he[ph];

    float* out_k = out + (size_t)k * ELEMS;
    const size_t img = (size_t)s_b * C_DIM * HW;

    if (pW <= 32) {
        // ---- Load phase: lane = w-column, uniform row loop, 16 channels ----
        float m[CPW];
        #pragma unroll
        for (int c = 0; c < CPW; ++c) m[c] = -CUDART_INF_F;

        const bool lw = (lane < pW);
        const float* base = x + img + (size_t)c0 * HW + w0 + lane;
        for (int h = hs; h < he; ++h) {
            const float* rowp = base + h * W_DIM;
            #pragma unroll
            for (int c = 0; c < CPW; ++c) {
                if (lw) m[c] = fmaxf(m[c], rowp[c * HW]);
            }
        }

        // ---- Stash per-column row-maxes ----
        #pragma unroll
        for (int c = 0; c < CPW; ++c) s_m[wid][c][lane] = m[c];
        __syncwarp();

        // ---- Compute phase: 112 outputs per warp ----
        #pragma unroll
        for (int p2 = 0; p2 < 4; ++p2) {
            const int o = p2 * 32 + lane;
            if (o < CPW * P) {
                const int c   = o / P;
                const int pw  = o - c * P;
                const int wsr = s_ws[pw] - w0;
                const int span = s_we[pw] - s_ws[pw];

                float v = -CUDART_INF_F;
                if (maxspan <= 4) {
                    #pragma unroll
                    for (int dw = 0; dw < 4; ++dw) {
                        if (dw < span) v = fmaxf(v, s_m[wid][c][wsr + dw]);
                    }
                } else {
                    for (int dw = 0; dw < span; ++dw) {
                        v = fmaxf(v, s_m[wid][c][wsr + dw]);
                    }
                }
                const bool valid = (he > hs) && (span > 0);
                out_k[(size_t)(c0 + c) * PP + ph * P + pw] = valid ? v : 0.0f;
            }
        }
    } else {
        // ---- Fallback: direct gather (ROI patch wider than 32 cells) ----
        for (int o = lane; o < CPW * PP; o += 32) {
            const int c   = o / PP;
            const int pos = o - c * PP;
            const int ph2 = pos / P;
            const int pw2 = pos - ph2 * P;

            const int bhs = s_hs[ph2], bhe = s_he[ph2];
            const int bws = s_ws[pw2], bwe = s_we[pw2];

            float mv = 0.0f;
            if (bhe > bhs && bwe > bws) {
                mv = -CUDART_INF_F;
                const float* p0 = x + img + (size_t)(c0 + c) * HW;
                for (int h = bhs; h < bhe; ++h) {
                    const float* row = p0 + h * W_DIM;
                    for (int w = bws; w < bwe; ++w) mv = fmaxf(mv, row[w]);
                }
            }
            out_k[(size_t)(c0 + c) * PP + pos] = mv;
        }
    }
}

extern "C" void kernel_launch(void* const* d_in, const int* in_sizes, int n_in,
                              void* d_out, int out_size)
{
    const float* x    = (const float*)d_in[0];
    const float* rois = (const float*)d_in[1];
    float* out        = (float*)d_out;

    int K = out_size / ELEMS;   // 256
    roipool_kernel<<<K * BLOCKS_PER_ROI, 256>>>(x, rois, out);
}

// round 10
// speedup vs baseline: 2.2447x; 1.0665x over previous
#include <cuda_runtime.h>
#include <math_constants.h>

// RoIPool: input (N=2, C=256, H=50, W=50) f32, rois (K=256, 5) f32
// output (K, C, 7, 7) f32. scale = 0.0625, P = 7.
//
// R9: warp-independent row-max factorization.
// Warp = (ROI, 8-channel group, ph). No block barriers: each warp
// computes bin bounds in lanes 0-6 and distributes via shuffles.
// Load phase (pW<=16 fast path): lanes 0-15 = row h, lanes 16-31 =
// row h+1 -> 2 rows per coalesced LDG, column-max folded with one
// shfl_xor(16) per channel. Stash 16 col-maxes per channel to a
// padded smem strip (stride 33, conflict-light), then 56 outputs
// (8c x 7pw) computed by lanes 0-27 in 2 rounds, <=4 predicated LDS
// each. CPW=8 keeps regs ~30 -> full occupancy (R8 was capped at 75%
// by m[16]). Block-uniform fallback covers span>4 / pW>32.

#define P 7
#define PP 49
#define C_DIM 256
#define H_DIM 50
#define W_DIM 50
#define HW 2500
#define SCALE 0.0625f
#define ELEMS (C_DIM * PP)     // 12544 per ROI
#define CPW 8                  // channels per warp
#define BLOCKS_PER_ROI 28      // 28 blocks * 8 warps = 224 = 32cg * 7ph

__global__ __launch_bounds__(256) void roipool_kernel(const float* __restrict__ x,
                                                      const float* __restrict__ rois,
                                                      float* __restrict__ out)
{
    const int k    = blockIdx.x / BLOCKS_PER_ROI;
    const int part = blockIdx.x - k * BLOCKS_PER_ROI;
    const int tid  = threadIdx.x;
    const int wid  = tid >> 5;
    const int lane = tid & 31;

    __shared__ float s_m[8][CPW][33];   // 8.25 KB

    const int task = part * 8 + wid;    // 0..223
    const int cg   = task / P;          // 0..31
    const int ph   = task - cg * P;

    // ---- Per-warp bound computation (lanes 0-6 meaningful) ----
    const float* r = rois + k * 5;
    const int   b  = (int)r[0];
    const float x1 = rintf(r[1] * SCALE);
    const float y1 = rintf(r[2] * SCALE);
    const float x2 = rintf(r[3] * SCALE);
    const float y2 = rintf(r[4] * SCALE);
    const float bin_w = fmaxf(x2 - x1 + 1.0f, 1.0f) * (1.0f / P);
    const float bin_h = fmaxf(y2 - y1 + 1.0f, 1.0f) * (1.0f / P);

    const float p = (float)(lane < P ? lane : 0);
    const int hs_l = (int)fminf(fmaxf(floorf(p * bin_h) + y1, 0.0f), (float)H_DIM);
    const int he_l = (int)fminf(fmaxf(ceilf((p + 1.0f) * bin_h) + y1, 0.0f), (float)H_DIM);
    const int ws_l = (int)fminf(fmaxf(floorf(p * bin_w) + x1, 0.0f), (float)W_DIM);
    const int we_l = (int)fminf(fmaxf(ceilf((p + 1.0f) * bin_w) + x1, 0.0f), (float)W_DIM);

    const unsigned FULL = 0xFFFFFFFFu;
    const int hs = __shfl_sync(FULL, hs_l, ph);
    const int he = __shfl_sync(FULL, he_l, ph);
    const int w0 = __shfl_sync(FULL, ws_l, 0);
    const int pW = __shfl_sync(FULL, we_l, P - 1) - w0;

    const bool bad_l = (lane < P) && ((he_l - hs_l > 4) || (we_l - ws_l > 4));
    const bool fallback = (__ballot_sync(FULL, bad_l) != 0) || (pW > 32);

    // Precompute compute-phase window params for both rounds (converged shfls).
    const int o0 = lane, o1 = lane + 28;
    const int c_r0 = o0 / 7, pw_r0 = o0 - c_r0 * 7;
    const int c_r1 = o1 / 7, pw_r1 = o1 - c_r1 * 7;
    const int ws0 = __shfl_sync(FULL, ws_l, pw_r0);
    const int we0 = __shfl_sync(FULL, we_l, pw_r0);
    const int ws1 = __shfl_sync(FULL, ws_l, pw_r1);
    const int we1 = __shfl_sync(FULL, we_l, pw_r1);

    const int c0 = cg * CPW;
    const float* base = x + ((size_t)b * C_DIM + c0) * HW;
    float* out_base   = out + (size_t)k * ELEMS + (size_t)c0 * PP + ph * P;

    if (!fallback) {
        float m[CPW];
        #pragma unroll
        for (int c = 0; c < CPW; ++c) m[c] = -CUDART_INF_F;

        if (pW <= 16) {
            // ---- 2-rows-per-LDG path ----
            const int  wl   = lane & 15;
            const int  hofs = lane >> 4;
            const bool lw   = wl < pW;
            const float* g  = base + (hs + hofs) * W_DIM + w0 + wl;
            #pragma unroll
            for (int rr = 0; rr < 4; rr += 2) {
                const bool ok = lw && (hs + hofs + rr < he);
                #pragma unroll
                for (int c = 0; c < CPW; ++c)
                    if (ok) m[c] = fmaxf(m[c], g[c * HW + rr * W_DIM]);
            }
            #pragma unroll
            for (int c = 0; c < CPW; ++c)
                m[c] = fmaxf(m[c], __shfl_xor_sync(FULL, m[c], 16));
            if (lane < 16) {
                #pragma unroll
                for (int c = 0; c < CPW; ++c) s_m[wid][c][lane] = m[c];
            }
        } else {
            // ---- 1-row path (16 < pW <= 32) ----
            const bool lw  = lane < pW;
            const float* g = base + hs * W_DIM + w0 + lane;
            #pragma unroll
            for (int rr = 0; rr < 4; ++rr) {
                const bool ok = lw && (hs + rr < he);
                #pragma unroll
                for (int c = 0; c < CPW; ++c)
                    if (ok) m[c] = fmaxf(m[c], g[c * HW + rr * W_DIM]);
            }
            #pragma unroll
            for (int c = 0; c < CPW; ++c) s_m[wid][c][lane] = m[c];
        }
        __syncwarp();

        // ---- Compute phase: 56 outputs, lanes 0-27, 2 rounds ----
        const bool hvalid = he > hs;
        if (lane < 28) {
            {
                const int wsr = ws0 - w0, span = we0 - ws0;
                float v = -CUDART_INF_F;
                #pragma unroll
                for (int dw = 0; dw < 4; ++dw)
                    if (dw < span) v = fmaxf(v, s_m[wid][c_r0][wsr + dw]);
                out_base[c_r0 * PP + pw_r0] = (hvalid && span > 0) ? v : 0.0f;
            }
            {
                const int wsr = ws1 - w0, span = we1 - ws1;
                float v = -CUDART_INF_F;
                #pragma unroll
                for (int dw = 0; dw < 4; ++dw)
                    if (dw < span) v = fmaxf(v, s_m[wid][c_r1][wsr + dw]);
                out_base[c_r1 * PP + pw_r1] = (hvalid && span > 0) ? v : 0.0f;
            }
        }
    } else {
        // ---- Fallback: direct gather, per-lane bounds recompute ----
        for (int o = lane; o < CPW * P; o += 32) {
            const int c  = o / 7;
            const int pw = o - c * 7;
            const float pf = (float)pw;
            const int ws = (int)fminf(fmaxf(floorf(pf * bin_w) + x1, 0.0f), (float)W_DIM);
            const int we = (int)fminf(fmaxf(ceilf((pf + 1.0f) * bin_w) + x1, 0.0f), (float)W_DIM);

            float mv = 0.0f;
            if (he > hs && we > ws) {
                mv = -CUDART_INF_F;
                const float* p0 = base + (size_t)c * HW;
                for (int h = hs; h < he; ++h) {
                    const float* row = p0 + h * W_DIM;
                    for (int w = ws; w < we; ++w) mv = fmaxf(mv, row[w]);
                }
            }
            out_base[c * PP + pw] = mv;
        }
    }
}

extern "C" void kernel_launch(void* const* d_in, const int* in_sizes, int n_in,
                              void* d_out, int out_size)
{
    const float* x    = (const float*)d_in[0];
    const float* rois = (const float*)d_in[1];
    float* out        = (float*)d_out;

    int K = out_size / ELEMS;   // 256
    roipool_kernel<<<K * BLOCKS_PER_ROI, 256>>>(x, rois, out);
}

// round 11
// speedup vs baseline: 2.5665x; 1.1434x over previous
#include <cuda_runtime.h>
#include <math_constants.h>

// RoIPool: input (N=2, C=256, H=50, W=50) f32, rois (K=256, 5) f32
// output (K, C, 7, 7) f32. scale = 0.0625, P = 7.
//
// R10 = R6 (best: direct gather, CPT=4, smem-hoisted bounds) with one
// change: work items ordered (ph, cg, pw) with ph slowest. 448 items
// per ph = exactly 14 warps, so every warp has a UNIFORM ph:
//  - hs/he warp-uniform -> h-loop is a uniform branch (rows outside the
//    window are skipped entirely, not predicated off lane-by-lane)
//  - per-LDG lane addresses collapse from a ~12-row scatter (R6) to
//    ~5 channel-groups x <=72B row spans -> ~half the L1 wavefronts.

#define P 7
#define PP 49
#define C_DIM 256
#define H_DIM 50
#define W_DIM 50
#define HW 2500
#define SCALE 0.0625f
#define ELEMS (C_DIM * PP)          // 12544 outputs per ROI
#define CPT 4                       // channels per thread
#define NCG (C_DIM / CPT)           // 64 channel groups
#define WORK_PER_ROI (P * NCG * P)  // 3136
#define BLOCKS_PER_ROI 13           // 13*256 = 3328 >= 3136
#define SPAN 4

__global__ __launch_bounds__(256) void roipool_kernel(const float* __restrict__ x,
                                                      const float* __restrict__ rois,
                                                      float* __restrict__ out)
{
    const int k    = blockIdx.x / BLOCKS_PER_ROI;
    const int part = blockIdx.x - k * BLOCKS_PER_ROI;

    __shared__ int s_hs[P], s_he[P], s_ws[P], s_we[P];
    __shared__ int s_b;

    if (threadIdx.x < P) {
        const float* r = rois + k * 5;
        float x1 = rintf(r[1] * SCALE);
        float y1 = rintf(r[2] * SCALE);
        float x2 = rintf(r[3] * SCALE);
        float y2 = rintf(r[4] * SCALE);

        float bin_w = fmaxf(x2 - x1 + 1.0f, 1.0f) * (1.0f / P);
        float bin_h = fmaxf(y2 - y1 + 1.0f, 1.0f) * (1.0f / P);

        float p = (float)threadIdx.x;
        s_hs[threadIdx.x] = (int)fminf(fmaxf(floorf(p * bin_h) + y1, 0.0f), (float)H_DIM);
        s_he[threadIdx.x] = (int)fminf(fmaxf(ceilf((p + 1.0f) * bin_h) + y1, 0.0f), (float)H_DIM);
        s_ws[threadIdx.x] = (int)fminf(fmaxf(floorf(p * bin_w) + x1, 0.0f), (float)W_DIM);
        s_we[threadIdx.x] = (int)fminf(fmaxf(ceilf((p + 1.0f) * bin_w) + x1, 0.0f), (float)W_DIM);
        if (threadIdx.x == 0) s_b = (int)rois[k * 5];
    }
    __syncthreads();

    const int i = part * 256 + threadIdx.x;
    if (i >= WORK_PER_ROI) return;

    // (ph, cg, pw), ph slowest: 448 = 14 warps per ph -> warp-uniform ph.
    const int ph  = i / (NCG * P);
    const int rem = i - ph * (NCG * P);
    const int cg  = rem / P;
    const int pw  = rem - cg * P;

    const int hs = s_hs[ph], he = s_he[ph];      // warp-uniform
    const int ws = s_ws[pw], we = s_we[pw];
    const bool valid = (he > hs) && (we > ws);

    const float* base = x + ((size_t)s_b * C_DIM + cg * CPT) * HW;

    float m[CPT];
    #pragma unroll
    for (int ch = 0; ch < CPT; ++ch) m[ch] = -CUDART_INF_F;

    if (he - hs <= SPAN && we - ws <= SPAN) {
        // Fast path: uniform h branches, predicated 4-wide window.
        #pragma unroll
        for (int dh = 0; dh < SPAN; ++dh) {
            if (hs + dh < he) {                     // warp-uniform branch
                const float* row = base + (hs + dh) * W_DIM + ws;
                #pragma unroll
                for (int dw = 0; dw < SPAN; ++dw) {
                    const bool ok = (ws + dw < we);
                    #pragma unroll
                    for (int ch = 0; ch < CPT; ++ch) {
                        if (ok) m[ch] = fmaxf(m[ch], row[ch * HW + dw]);
                    }
                }
            }
        }
    } else {
        // Fallback: dynamic bounds (not hit by this data distribution).
        for (int h = hs; h < he; ++h) {
            const float* row = base + h * W_DIM;
            for (int w = ws; w < we; ++w) {
                #pragma unroll
                for (int ch = 0; ch < CPT; ++ch) {
                    m[ch] = fmaxf(m[ch], row[ch * HW + w]);
                }
            }
        }
    }

    float* o = out + (size_t)k * ELEMS + (size_t)(cg * CPT) * PP + ph * P + pw;
    #pragma unroll
    for (int ch = 0; ch < CPT; ++ch) {
        o[ch * PP] = valid ? m[ch] : 0.0f;
    }
}

extern "C" void kernel_launch(void* const* d_in, const int* in_sizes, int n_in,
                              void* d_out, int out_size)
{
    const float* x    = (const float*)d_in[0];
    const float* rois = (const float*)d_in[1];
    float* out        = (float*)d_out;

    int K = out_size / ELEMS;   // 256
    roipool_kernel<<<K * BLOCKS_PER_ROI, 256>>>(x, rois, out);
}